// round 14
// baseline (speedup 1.0000x reference)
#include <cuda_runtime.h>
#include <cuda_bf16.h>
#include <math.h>

// Problem constants (fixed by the reference)
#define NTOK 4096      // B*T = 2*2048
#define DIM  768
#define NEXP 8
#define FDIM 3072
#define TOPK 2

// ---------------------------------------------------------------------------
// Scratch (device globals; allocation-free per harness rules)
// ---------------------------------------------------------------------------
__device__ int   g_count[NEXP];                 // tokens per expert
__device__ int   g_off[NEXP + 1];               // exclusive scan of counts
__device__ int   g_tok[NEXP * NTOK];            // per-expert gathered token ids
__device__ int   g_t_e[NTOK];                   // e0 | (e1<<8) per token
__device__ int   g_t_slot[NTOK * 2];            // slot within expert list
__device__ float g_t_gate[NTOK * 2];            // normalized top-2 gates
__device__ float g_h[2 * NTOK * FDIM];          // hidden (8192 x 3072) ~100 MB
__device__ float g_y[2 * NTOK * DIM];           // expert outputs (8192 x 768) ~25 MB

// ---------------------------------------------------------------------------
// Kernel 0: zero per-expert counters
// ---------------------------------------------------------------------------
__global__ void zero_counts_kernel() {
    int t = threadIdx.x;
    if (t < NEXP) g_count[t] = 0;
}

// ---------------------------------------------------------------------------
// Kernel 1: gating. One warp per token.
//   logits = x @ gate_w + gate_b ; softmax ; top-2 ; renormalize ; dispatch.
// ---------------------------------------------------------------------------
__global__ void gating_kernel(const float* __restrict__ x,
                              const float* __restrict__ gw,
                              const float* __restrict__ gb) {
    int warp = (blockIdx.x * blockDim.x + threadIdx.x) >> 5;
    int lane = threadIdx.x & 31;
    if (warp >= NTOK) return;

    const float* xr = x + (size_t)warp * DIM;
    float acc[NEXP];
#pragma unroll
    for (int e = 0; e < NEXP; e++) acc[e] = 0.f;

    for (int d = lane; d < DIM; d += 32) {
        float xv = xr[d];
        const float* gwr = gw + d * NEXP;
#pragma unroll
        for (int e = 0; e < NEXP; e++) acc[e] += xv * gwr[e];
    }
#pragma unroll
    for (int e = 0; e < NEXP; e++) {
#pragma unroll
        for (int o = 16; o > 0; o >>= 1)
            acc[e] += __shfl_xor_sync(0xffffffffu, acc[e], o);
    }

    if (lane == 0) {
        float p[NEXP];
        float mx = -1e30f;
#pragma unroll
        for (int e = 0; e < NEXP; e++) {
            p[e] = acc[e] + gb[e];
            mx = fmaxf(mx, p[e]);
        }
        float s = 0.f;
#pragma unroll
        for (int e = 0; e < NEXP; e++) { p[e] = expf(p[e] - mx); s += p[e]; }
        float inv_s = 1.f / s;
#pragma unroll
        for (int e = 0; e < NEXP; e++) p[e] *= inv_s;

        // top-2 (ties -> lower index first, matching lax.top_k)
        int e0 = 0;
#pragma unroll
        for (int e = 1; e < NEXP; e++) if (p[e] > p[e0]) e0 = e;
        int e1 = -1;
#pragma unroll
        for (int e = 0; e < NEXP; e++) {
            if (e == e0) continue;
            if (e1 < 0 || p[e] > p[e1]) e1 = e;
        }
        float gv0 = p[e0], gv1 = p[e1];
        float inv = 1.f / (gv0 + gv1 + 1e-9f);
        gv0 *= inv; gv1 *= inv;

        int s0 = atomicAdd(&g_count[e0], 1);
        int s1 = atomicAdd(&g_count[e1], 1);
        g_tok[e0 * NTOK + s0] = warp;
        g_tok[e1 * NTOK + s1] = warp;
        g_t_e[warp] = e0 | (e1 << 8);
        g_t_slot[warp * 2 + 0] = s0;
        g_t_slot[warp * 2 + 1] = s1;
        g_t_gate[warp * 2 + 0] = gv0;
        g_t_gate[warp * 2 + 1] = gv1;
    }
}

// ---------------------------------------------------------------------------
// Kernel 2: exclusive scan of 8 counts (single thread; trivial)
// ---------------------------------------------------------------------------
__global__ void scan_kernel() {
    if (threadIdx.x == 0) {
        int acc = 0;
        g_off[0] = 0;
        for (int e = 0; e < NEXP; e++) { acc += g_count[e]; g_off[e + 1] = acc; }
    }
}

// ---------------------------------------------------------------------------
// Kernel 3/4: tiled SGEMM for the expert FFN.
//   PHASE 1: C = gelu(gather(x) @ w1[e] + b1[e])      K=768,  Nd=3072 -> g_h
//   PHASE 2: C =        h        @ w2[e] + b2[e]      K=3072, Nd=768  -> g_y
// BM=BN=128, BK=16, 256 threads, 8x8 register tile.
// ---------------------------------------------------------------------------
__device__ __forceinline__ float gelu_exact(float v) {
    return 0.5f * v * (1.0f + erff(v * 0.70710678118654752440f));
}

template <int PHASE>
__global__ void __launch_bounds__(256, 2)
ffn_gemm_kernel(const float* __restrict__ Ax,
                const float* __restrict__ Bw,
                const float* __restrict__ bias) {
    constexpr int Kd = (PHASE == 1) ? DIM : FDIM;
    constexpr int Nd = (PHASE == 1) ? FDIM : DIM;
    constexpr bool GELU = (PHASE == 1);
    constexpr bool GATHER = (PHASE == 1);

    const int e = blockIdx.z;
    const int cnt = g_count[e];
    const int m0 = blockIdx.x * 128;
    if (m0 >= cnt) return;
    const int n0 = blockIdx.y * 128;
    const int off = g_off[e];

    const float* Be = Bw + (size_t)e * Kd * Nd;
    const float* be = bias + (size_t)e * Nd;
    float* C = GELU ? g_h : g_y;
    const float* A = GATHER ? Ax : g_h;

    __shared__ float As[16][128];
    __shared__ float Bs[16][128];

    const int tid = threadIdx.x;
    const int tx = tid & 15;       // column group
    const int ty = tid >> 4;       // row group

    // ---- A load mapping: each thread owns row (tid>>1), 2 float4 groups ----
    const int arow_l = tid >> 1;                 // 0..127
    const int ac0 = (tid & 1) * 2;               // {0,1} or {2,3}
    int am = m0 + arow_l;
    int asrc = (am < cnt) ? am : 0;              // safe clamp (cnt >= 1 here)
    const float* arow_ptr;
    if (GATHER)
        arow_ptr = A + (size_t)g_tok[e * NTOK + asrc] * Kd;
    else
        arow_ptr = A + (size_t)(off + asrc) * Kd;

    // ---- B load mapping: row tid>>4 (0..15), 2 consecutive float4 ----
    const int brow = tid >> 4;

    float accv[8][8];
#pragma unroll
    for (int i = 0; i < 8; i++)
#pragma unroll
        for (int j = 0; j < 8; j++) accv[i][j] = 0.f;

    for (int k0 = 0; k0 < Kd; k0 += 16) {
        // A tile (transposed into As[k][m])
#pragma unroll
        for (int i = 0; i < 2; i++) {
            int c4 = ac0 + i;
            float4 v = *(const float4*)(arow_ptr + k0 + c4 * 4);
            As[c4 * 4 + 0][arow_l] = v.x;
            As[c4 * 4 + 1][arow_l] = v.y;
            As[c4 * 4 + 2][arow_l] = v.z;
            As[c4 * 4 + 3][arow_l] = v.w;
        }
        // B tile
#pragma unroll
        for (int i = 0; i < 2; i++) {
            int c = (tid * 2 + i) & 31;
            float4 v = *(const float4*)(Be + (size_t)(k0 + brow) * Nd + n0 + c * 4);
            *(float4*)&Bs[brow][c * 4] = v;
        }
        __syncthreads();

#pragma unroll
        for (int k = 0; k < 16; k++) {
            float a[8], b[8];
            *(float4*)(a + 0) = *(const float4*)&As[k][ty * 8 + 0];
            *(float4*)(a + 4) = *(const float4*)&As[k][ty * 8 + 4];
            *(float4*)(b + 0) = *(const float4*)&Bs[k][tx * 8 + 0];
            *(float4*)(b + 4) = *(const float4*)&Bs[k][tx * 8 + 4];
#pragma unroll
            for (int i = 0; i < 8; i++)
#pragma unroll
                for (int j = 0; j < 8; j++)
                    accv[i][j] += a[i] * b[j];
        }
        __syncthreads();
    }

    // epilogue: bias (+gelu), write C rows [off+m, Nd]
#pragma unroll
    for (int i = 0; i < 8; i++) {
        int m = m0 + ty * 8 + i;
        if (m >= cnt) continue;
        float* crow = C + (size_t)(off + m) * Nd + n0 + tx * 8;
        const float* brow_b = be + n0 + tx * 8;
#pragma unroll
        for (int j = 0; j < 8; j++) {
            float v = accv[i][j] + brow_b[j];
            if (GELU) v = gelu_exact(v);
            crow[j] = v;
        }
    }
}

// ---------------------------------------------------------------------------
// Kernel 5: combine. out[n] = g0 * y[row0] + g1 * y[row1]. Writes every
// element exactly once -> deterministic, no init needed.
// ---------------------------------------------------------------------------
__global__ void combine_kernel(float* __restrict__ out) {
    int idx = blockIdx.x * blockDim.x + threadIdx.x;   // float4 granularity
    const int per_row = DIM / 4;                        // 192
    if (idx >= NTOK * per_row) return;
    int n = idx / per_row;
    int c = idx - n * per_row;

    int ee = g_t_e[n];
    int e0 = ee & 0xff;
    int e1 = ee >> 8;
    int r0 = g_off[e0] + g_t_slot[n * 2 + 0];
    int r1 = g_off[e1] + g_t_slot[n * 2 + 1];
    float gv0 = g_t_gate[n * 2 + 0];
    float gv1 = g_t_gate[n * 2 + 1];

    float4 y0 = *(const float4*)&g_y[(size_t)r0 * DIM + c * 4];
    float4 y1 = *(const float4*)&g_y[(size_t)r1 * DIM + c * 4];
    float4 o;
    o.x = gv0 * y0.x + gv1 * y1.x;
    o.y = gv0 * y0.y + gv1 * y1.y;
    o.z = gv0 * y0.z + gv1 * y1.z;
    o.w = gv0 * y0.w + gv1 * y1.w;
    ((float4*)out)[idx] = o;
}

// ---------------------------------------------------------------------------
// Launch
// ---------------------------------------------------------------------------
extern "C" void kernel_launch(void* const* d_in, const int* in_sizes, int n_in,
                              void* d_out, int out_size) {
    const float* x      = (const float*)d_in[0];   // [2,2048,768]
    const float* gate_w = (const float*)d_in[1];   // [768,8]
    const float* gate_b = (const float*)d_in[2];   // [8]
    const float* w1     = (const float*)d_in[3];   // [8,768,3072]
    const float* b1     = (const float*)d_in[4];   // [8,3072]
    const float* w2     = (const float*)d_in[5];   // [8,3072,768]
    const float* b2     = (const float*)d_in[6];   // [8,768]
    float* out          = (float*)d_out;           // [2,2048,768]

    // 0) reset dispatch counters
    zero_counts_kernel<<<1, 32>>>();

    // 1) gating: one warp per token, 8 warps per block
    gating_kernel<<<NTOK / 8, 256>>>(x, gate_w, gate_b);

    // 2) offsets
    scan_kernel<<<1, 32>>>();

    // 3) FFN1: h = gelu(gather(x) @ w1 + b1)
    {
        dim3 grid(NTOK / 128, FDIM / 128, NEXP);   // (32, 24, 8)
        ffn_gemm_kernel<1><<<grid, 256>>>(x, w1, b1);
    }

    // 4) FFN2: y = h @ w2 + b2
    {
        dim3 grid(NTOK / 128, DIM / 128, NEXP);    // (32, 6, 8)
        ffn_gemm_kernel<2><<<grid, 256>>>(nullptr, w2, b2);
    }

    // 5) combine into output
    {
        int total = NTOK * (DIM / 4);
        combine_kernel<<<(total + 255) / 256, 256>>>(out);
    }
}

// round 15
// speedup vs baseline: 1.0041x; 1.0041x over previous
#include <cuda_runtime.h>
#include <cuda_bf16.h>
#include <math.h>

// Problem constants (fixed by the reference)
#define NTOK 4096      // B*T = 2*2048
#define DIM  768
#define NEXP 8
#define FDIM 3072
#define TOPK 2

// ---------------------------------------------------------------------------
// Scratch (device globals; allocation-free per harness rules)
// ---------------------------------------------------------------------------
__device__ int   g_count[NEXP];                 // tokens per expert
__device__ int   g_off[NEXP + 1];               // exclusive scan of counts
__device__ int   g_tok[NEXP * NTOK];            // per-expert gathered token ids
__device__ int   g_t_e[NTOK];                   // e0 | (e1<<8) per token
__device__ int   g_t_slot[NTOK * 2];            // slot within expert list
__device__ float g_t_gate[NTOK * 2];            // normalized top-2 gates
__device__ float g_h[2 * NTOK * FDIM];          // hidden (8192 x 3072) ~100 MB
__device__ float g_y[2 * NTOK * DIM];           // expert outputs (8192 x 768) ~25 MB

// ---------------------------------------------------------------------------
// Kernel 0: zero per-expert counters
// ---------------------------------------------------------------------------
__global__ void zero_counts_kernel() {
    int t = threadIdx.x;
    if (t < NEXP) g_count[t] = 0;
}

// ---------------------------------------------------------------------------
// Kernel 1: gating. One warp per token.
//   logits = x @ gate_w + gate_b ; softmax ; top-2 ; renormalize ; dispatch.
// ---------------------------------------------------------------------------
__global__ void gating_kernel(const float* __restrict__ x,
                              const float* __restrict__ gw,
                              const float* __restrict__ gb) {
    int warp = (blockIdx.x * blockDim.x + threadIdx.x) >> 5;
    int lane = threadIdx.x & 31;
    if (warp >= NTOK) return;

    const float* xr = x + (size_t)warp * DIM;
    float acc[NEXP];
#pragma unroll
    for (int e = 0; e < NEXP; e++) acc[e] = 0.f;

    for (int d = lane; d < DIM; d += 32) {
        float xv = xr[d];
        const float* gwr = gw + d * NEXP;
#pragma unroll
        for (int e = 0; e < NEXP; e++) acc[e] += xv * gwr[e];
    }
#pragma unroll
    for (int e = 0; e < NEXP; e++) {
#pragma unroll
        for (int o = 16; o > 0; o >>= 1)
            acc[e] += __shfl_xor_sync(0xffffffffu, acc[e], o);
    }

    if (lane == 0) {
        float p[NEXP];
        float mx = -1e30f;
#pragma unroll
        for (int e = 0; e < NEXP; e++) {
            p[e] = acc[e] + gb[e];
            mx = fmaxf(mx, p[e]);
        }
        float s = 0.f;
#pragma unroll
        for (int e = 0; e < NEXP; e++) { p[e] = expf(p[e] - mx); s += p[e]; }
        float inv_s = 1.f / s;
#pragma unroll
        for (int e = 0; e < NEXP; e++) p[e] *= inv_s;

        // top-2 (ties -> lower index first, matching lax.top_k)
        int e0 = 0;
#pragma unroll
        for (int e = 1; e < NEXP; e++) if (p[e] > p[e0]) e0 = e;
        int e1 = -1;
#pragma unroll
        for (int e = 0; e < NEXP; e++) {
            if (e == e0) continue;
            if (e1 < 0 || p[e] > p[e1]) e1 = e;
        }
        float gv0 = p[e0], gv1 = p[e1];
        float inv = 1.f / (gv0 + gv1 + 1e-9f);
        gv0 *= inv; gv1 *= inv;

        int s0 = atomicAdd(&g_count[e0], 1);
        int s1 = atomicAdd(&g_count[e1], 1);
        g_tok[e0 * NTOK + s0] = warp;
        g_tok[e1 * NTOK + s1] = warp;
        g_t_e[warp] = e0 | (e1 << 8);
        g_t_slot[warp * 2 + 0] = s0;
        g_t_slot[warp * 2 + 1] = s1;
        g_t_gate[warp * 2 + 0] = gv0;
        g_t_gate[warp * 2 + 1] = gv1;
    }
}

// ---------------------------------------------------------------------------
// Kernel 2: exclusive scan of 8 counts (single thread; trivial)
// ---------------------------------------------------------------------------
__global__ void scan_kernel() {
    if (threadIdx.x == 0) {
        int acc = 0;
        g_off[0] = 0;
        for (int e = 0; e < NEXP; e++) { acc += g_count[e]; g_off[e + 1] = acc; }
    }
}

// ---------------------------------------------------------------------------
// Kernel 3/4: tiled SGEMM for the expert FFN.
//   PHASE 1: C = gelu(gather(x) @ w1[e] + b1[e])      K=768,  Nd=3072 -> g_h
//   PHASE 2: C =        h        @ w2[e] + b2[e]      K=3072, Nd=768  -> g_y
// BM=BN=128, BK=16, 256 threads, 8x8 register tile.
// ---------------------------------------------------------------------------
__device__ __forceinline__ float gelu_exact(float v) {
    return 0.5f * v * (1.0f + erff(v * 0.70710678118654752440f));
}

template <int PHASE>
__global__ void __launch_bounds__(256, 2)
ffn_gemm_kernel(const float* __restrict__ Ax,
                const float* __restrict__ Bw,
                const float* __restrict__ bias) {
    constexpr int Kd = (PHASE == 1) ? DIM : FDIM;
    constexpr int Nd = (PHASE == 1) ? FDIM : DIM;
    constexpr bool GELU = (PHASE == 1);
    constexpr bool GATHER = (PHASE == 1);

    const int e = blockIdx.z;
    const int cnt = g_count[e];
    const int m0 = blockIdx.x * 128;
    if (m0 >= cnt) return;
    const int n0 = blockIdx.y * 128;
    const int off = g_off[e];

    const float* Be = Bw + (size_t)e * Kd * Nd;
    const float* be = bias + (size_t)e * Nd;
    float* C = GELU ? g_h : g_y;
    const float* A = GATHER ? Ax : g_h;

    __shared__ float As[16][128];
    __shared__ float Bs[16][128];

    const int tid = threadIdx.x;
    const int tx = tid & 15;       // column group
    const int ty = tid >> 4;       // row group

    // ---- A load mapping: each thread owns row (tid>>1), 2 float4 groups ----
    const int arow_l = tid >> 1;                 // 0..127
    const int ac0 = (tid & 1) * 2;               // {0,1} or {2,3}
    int am = m0 + arow_l;
    int asrc = (am < cnt) ? am : 0;              // safe clamp (cnt >= 1 here)
    const float* arow_ptr;
    if (GATHER)
        arow_ptr = A + (size_t)g_tok[e * NTOK + asrc] * Kd;
    else
        arow_ptr = A + (size_t)(off + asrc) * Kd;

    // ---- B load mapping: row tid>>4 (0..15), 2 consecutive float4 ----
    const int brow = tid >> 4;

    float accv[8][8];
#pragma unroll
    for (int i = 0; i < 8; i++)
#pragma unroll
        for (int j = 0; j < 8; j++) accv[i][j] = 0.f;

    for (int k0 = 0; k0 < Kd; k0 += 16) {
        // A tile (transposed into As[k][m])
#pragma unroll
        for (int i = 0; i < 2; i++) {
            int c4 = ac0 + i;
            float4 v = *(const float4*)(arow_ptr + k0 + c4 * 4);
            As[c4 * 4 + 0][arow_l] = v.x;
            As[c4 * 4 + 1][arow_l] = v.y;
            As[c4 * 4 + 2][arow_l] = v.z;
            As[c4 * 4 + 3][arow_l] = v.w;
        }
        // B tile
#pragma unroll
        for (int i = 0; i < 2; i++) {
            int c = (tid * 2 + i) & 31;
            float4 v = *(const float4*)(Be + (size_t)(k0 + brow) * Nd + n0 + c * 4);
            *(float4*)&Bs[brow][c * 4] = v;
        }
        __syncthreads();

#pragma unroll
        for (int k = 0; k < 16; k++) {
            float a[8], b[8];
            *(float4*)(a + 0) = *(const float4*)&As[k][ty * 8 + 0];
            *(float4*)(a + 4) = *(const float4*)&As[k][ty * 8 + 4];
            *(float4*)(b + 0) = *(const float4*)&Bs[k][tx * 8 + 0];
            *(float4*)(b + 4) = *(const float4*)&Bs[k][tx * 8 + 4];
#pragma unroll
            for (int i = 0; i < 8; i++)
#pragma unroll
                for (int j = 0; j < 8; j++)
                    accv[i][j] += a[i] * b[j];
        }
        __syncthreads();
    }

    // epilogue: bias (+gelu), write C rows [off+m, Nd]
#pragma unroll
    for (int i = 0; i < 8; i++) {
        int m = m0 + ty * 8 + i;
        if (m >= cnt) continue;
        float* crow = C + (size_t)(off + m) * Nd + n0 + tx * 8;
        const float* brow_b = be + n0 + tx * 8;
#pragma unroll
        for (int j = 0; j < 8; j++) {
            float v = accv[i][j] + brow_b[j];
            if (GELU) v = gelu_exact(v);
            crow[j] = v;
        }
    }
}

// ---------------------------------------------------------------------------
// Kernel 5: combine. out[n] = g0 * y[row0] + g1 * y[row1]. Writes every
// element exactly once -> deterministic, no init needed.
// ---------------------------------------------------------------------------
__global__ void combine_kernel(float* __restrict__ out) {
    int idx = blockIdx.x * blockDim.x + threadIdx.x;   // float4 granularity
    const int per_row = DIM / 4;                        // 192
    if (idx >= NTOK * per_row) return;
    int n = idx / per_row;
    int c = idx - n * per_row;

    int ee = g_t_e[n];
    int e0 = ee & 0xff;
    int e1 = ee >> 8;
    int r0 = g_off[e0] + g_t_slot[n * 2 + 0];
    int r1 = g_off[e1] + g_t_slot[n * 2 + 1];
    float gv0 = g_t_gate[n * 2 + 0];
    float gv1 = g_t_gate[n * 2 + 1];

    float4 y0 = *(const float4*)&g_y[(size_t)r0 * DIM + c * 4];
    float4 y1 = *(const float4*)&g_y[(size_t)r1 * DIM + c * 4];
    float4 o;
    o.x = gv0 * y0.x + gv1 * y1.x;
    o.y = gv0 * y0.y + gv1 * y1.y;
    o.z = gv0 * y0.z + gv1 * y1.z;
    o.w = gv0 * y0.w + gv1 * y1.w;
    ((float4*)out)[idx] = o;
}

// ---------------------------------------------------------------------------
// Launch
// ---------------------------------------------------------------------------
extern "C" void kernel_launch(void* const* d_in, const int* in_sizes, int n_in,
                              void* d_out, int out_size) {
    const float* x      = (const float*)d_in[0];   // [2,2048,768]
    const float* gate_w = (const float*)d_in[1];   // [768,8]
    const float* gate_b = (const float*)d_in[2];   // [8]
    const float* w1     = (const float*)d_in[3];   // [8,768,3072]
    const float* b1     = (const float*)d_in[4];   // [8,3072]
    const float* w2     = (const float*)d_in[5];   // [8,3072,768]
    const float* b2     = (const float*)d_in[6];   // [8,768]
    float* out          = (float*)d_out;           // [2,2048,768]

    // 0) reset dispatch counters
    zero_counts_kernel<<<1, 32>>>();

    // 1) gating: one warp per token, 8 warps per block
    gating_kernel<<<NTOK / 8, 256>>>(x, gate_w, gate_b);

    // 2) offsets
    scan_kernel<<<1, 32>>>();

    // 3) FFN1: h = gelu(gather(x) @ w1 + b1)
    {
        dim3 grid(NTOK / 128, FDIM / 128, NEXP);   // (32, 24, 8)
        ffn_gemm_kernel<1><<<grid, 256>>>(x, w1, b1);
    }

    // 4) FFN2: y = h @ w2 + b2
    {
        dim3 grid(NTOK / 128, DIM / 128, NEXP);    // (32, 6, 8)
        ffn_gemm_kernel<2><<<grid, 256>>>(nullptr, w2, b2);
    }

    // 5) combine into output
    {
        int total = NTOK * (DIM / 4);
        combine_kernel<<<(total + 255) / 256, 256>>>(out);
    }
}